// round 12
// baseline (speedup 1.0000x reference)
#include <cuda_runtime.h>
#include <cuda_bf16.h>

#define N_PROP 128
#define N_GRIDP 216
#define G_TOT  27648
#define N_KEY  4096
#define C_FEAT 128
#define NS     16
#define K_RED  27648
#define KSPLIT 36
#define KCHUNK 768
#define NCHUNK 4608              // 2 * 27648 / 12
#define BQ_THREADS 512

typedef unsigned long long ull;

// ---------------- scratch ----------------
static __device__ float  d_grid[G_TOT * 3];
static __device__ float2 d_A[2][N_KEY * 32];    // A' = g1*A + b1, packed (c, c+32)
static __device__ int    d_idx[2][G_TOT * NS];
static __device__ int    d_cnt[2][G_TOT];
static __device__ float  d_perm[N_PROP * K_RED];
static __device__ float  d_partial[KSPLIT][N_PROP * 256];
static __device__ float  d_hbuf[N_PROP * 256];
static __device__ float  d_w2t[256 * 256];
static __device__ unsigned d_work;

// ---------------- f32x2 helpers ----------------
__device__ __forceinline__ ull splat2(float x) {
    ull r;
    asm("mov.b64 %0, {%1, %1};" : "=l"(r) : "f"(x));
    return r;
}
__device__ __forceinline__ void fma2(ull& acc, ull a, ull b) {
    asm("fma.rn.f32x2 %0, %1, %2, %0;" : "+l"(acc) : "l"(a), "l"(b));
}
__device__ __forceinline__ float2 unpack2(ull v) {
    float lo, hi;
    asm("mov.b64 {%0, %1}, %2;" : "=f"(lo), "=f"(hi) : "l"(v));
    return make_float2(lo, hi);
}
__device__ __forceinline__ ull d2u(double d) { return __double_as_longlong(d); }

// ---------------- k1: grid points (+ work counter reset) ----------------
__global__ void k_grid(const float* __restrict__ wlh, const float* __restrict__ center,
                       const float* __restrict__ yaw, const float* __restrict__ u)
{
    if (blockIdx.x == 0 && threadIdx.x == 0) d_work = 0u;
    int g = blockIdx.x * 256 + threadIdx.x;
    if (g >= G_TOT) return;
    int ni = g / N_GRIDP;
    float gx = u[g * 3 + 0] * wlh[ni * 3 + 0];
    float gy = u[g * 3 + 1] * wlh[ni * 3 + 1];
    float gz = u[g * 3 + 2] * wlh[ni * 3 + 2];
    float yv = yaw[ni];
    float c = cosf(yv), s = sinf(yv);
    float rx = c * gx - s * gy;
    float ry = s * gx + c * gy;
    d_grid[g * 3 + 0] = rx + center[ni * 3 + 0];
    d_grid[g * 3 + 1] = ry + center[ni * 3 + 1];
    d_grid[g * 3 + 2] = gz + center[ni * 3 + 2];
}

// ---------------- k2: per-keypoint A' = g1*(kp.w1[:3] + kf.w1[3:]) + b1 -------
__global__ void __launch_bounds__(256) k_A(const float* __restrict__ kp, const float* __restrict__ kf,
                                           const float* __restrict__ w1_0, const float* __restrict__ w1_1,
                                           const float* __restrict__ g1_0, const float* __restrict__ g1_1,
                                           const float* __restrict__ b1_0, const float* __restrict__ b1_1)
{
    __shared__ float w1s[64 * 131];
    extern __shared__ float kfs[];            // 128 c x 64 k = 32 KB dynamic
    const float* w1 = blockIdx.y ? w1_1 : w1_0;
    const float* g1 = blockIdx.y ? g1_1 : g1_0;
    const float* b1 = blockIdx.y ? b1_1 : b1_0;
    int tid = threadIdx.y * 32 + threadIdx.x;
    for (int i = tid; i < 64 * 131; i += 256) w1s[i] = w1[i];

    int kbase = blockIdx.x * 64;
    for (int e = tid; e < C_FEAT * 64; e += 256) {
        int c = e >> 6, kk = e & 63;
        kfs[c * 64 + kk] = kf[c * N_KEY + kbase + kk];
    }
    __syncthreads();

    int l = threadIdx.x;
    float g1lo = g1[l], g1hi = g1[l + 32];
    float b1lo = b1[l], b1hi = b1[l + 32];
#pragma unroll 1
    for (int t = 0; t < 8; t++) {
        int kk = t * 8 + threadIdx.y;
        int k = kbase + kk;
        float kx = kp[k * 3 + 0], ky = kp[k * 3 + 1], kz = kp[k * 3 + 2];
        float a0 = w1s[l * 131 + 0] * kx + w1s[l * 131 + 1] * ky + w1s[l * 131 + 2] * kz;
        float a1 = w1s[(l + 32) * 131 + 0] * kx + w1s[(l + 32) * 131 + 1] * ky + w1s[(l + 32) * 131 + 2] * kz;
#pragma unroll 4
        for (int c = 0; c < C_FEAT; c++) {
            float f = kfs[c * 64 + kk];
            a0 = fmaf(f, w1s[l * 131 + 3 + c], a0);
            a1 = fmaf(f, w1s[(l + 32) * 131 + 3 + c], a1);
        }
        d_A[blockIdx.y][k * 32 + l] = make_float2(fmaf(g1lo, a0, b1lo), fmaf(g1hi, a1, b1hi));
    }
}

// ---------------- k3: warp-cooperative ball query ----------------
__device__ __forceinline__ void bq_merge(int* __restrict__ out, int* __restrict__ cntout,
                                         int c, const int* h, int lane)
{
    const unsigned full = 0xffffffffu;
    int pre = c;
#pragma unroll
    for (int off = 1; off < 32; off <<= 1) {
        int t = __shfl_up_sync(full, pre, off);
        if (lane >= off) pre += t;
    }
    int excl = pre - c;
    int total = __shfl_sync(full, pre, 31);
    unsigned ball = __ballot_sync(full, c > 0);
    int myfirst = lane * 128 + h[0];
    int fl = (ball != 0u) ? (__ffs(ball) - 1) : 0;
    int f = __shfl_sync(full, myfirst, fl);
    if (ball == 0u) f = 0;
#pragma unroll 1
    for (int t = 0; t < c; t++) {
        int pos = excl + t;
        if (pos < NS) out[pos] = lane * 128 + h[t];
    }
    int tot16 = (total < NS) ? total : NS;
    for (int p = tot16 + lane; p < NS; p += 32) out[p] = f;
    if (lane == 0) *cntout = (tot16 > 0) ? tot16 : 1;
}

__global__ void __launch_bounds__(BQ_THREADS) k_ball(const float* __restrict__ kp)
{
    extern __shared__ float4 kpt[];   // [lane*129 + i], 4128 float4 = 66048 B
    int tid = threadIdx.x;
    for (int k = tid; k < N_KEY; k += BQ_THREADS) {
        int l = k >> 7, i = k & 127;
        float kx = kp[k * 3 + 0], ky = kp[k * 3 + 1], kz = kp[k * 3 + 2];
        kpt[l * 129 + i] = make_float4(kx, ky, kz, kx * kx + ky * ky + kz * kz);
    }
    __syncthreads();

    int lane = tid & 31, warp = tid >> 5;
    int g = blockIdx.x * (BQ_THREADS / 32) + warp;

    float gx = d_grid[g * 3 + 0], gy = d_grid[g * 3 + 1], gz = d_grid[g * 3 + 2];
    float gs = gx * gx + gy * gy + gz * gz;
    float m2x = -2.f * gx, m2y = -2.f * gy, m2z = -2.f * gz;

    int h0[NS], h1[NS];
    h0[0] = 0; h1[0] = 0;
    int c0 = 0, c1 = 0;
    const float4* my = kpt + lane * 129;

#pragma unroll 1
    for (int i = 0; i < 128; i += 4) {
        float4 v0 = my[i + 0];
        float4 v1 = my[i + 1];
        float4 v2 = my[i + 2];
        float4 v3 = my[i + 3];
        float d20 = fmaf(m2x, v0.x, fmaf(m2y, v0.y, fmaf(m2z, v0.z, gs + v0.w)));
        float d21 = fmaf(m2x, v1.x, fmaf(m2y, v1.y, fmaf(m2z, v1.z, gs + v1.w)));
        float d22 = fmaf(m2x, v2.x, fmaf(m2y, v2.y, fmaf(m2z, v2.z, gs + v2.w)));
        float d23 = fmaf(m2x, v3.x, fmaf(m2y, v3.y, fmaf(m2z, v3.z, gs + v3.w)));
        if (fminf(fminf(d20, d21), fminf(d22, d23)) < 2.56f) {   // rare
            if (d20 < 2.56f) { if (c1 < NS) h1[c1++] = i + 0; if (d20 < 0.64f && c0 < NS) h0[c0++] = i + 0; }
            if (d21 < 2.56f) { if (c1 < NS) h1[c1++] = i + 1; if (d21 < 0.64f && c0 < NS) h0[c0++] = i + 1; }
            if (d22 < 2.56f) { if (c1 < NS) h1[c1++] = i + 2; if (d22 < 0.64f && c0 < NS) h0[c0++] = i + 2; }
            if (d23 < 2.56f) { if (c1 < NS) h1[c1++] = i + 3; if (d23 < 0.64f && c0 < NS) h0[c0++] = i + 3; }
        }
    }
    bq_merge(&d_idx[0][g * NS], &d_cnt[0][g], c0, h0, lane);
    bq_merge(&d_idx[1][g * NS], &d_cnt[1][g], c1, h1, lane);
}

// ---------------- k4: branch MLP, warp-pair per gridpoint, 384 thr ------------
// warp w: gridpoint sub-index (w>>1), half = w&1. Lane owns output o=half*32+lane
// (w2 row = 64 floats = 32 f32x2 regs). Both halves duplicate the cheap h compute.
__global__ void __launch_bounds__(384, 1) k_branch(
    const float* __restrict__ w1_0, const float* __restrict__ g1_0,
    const float* __restrict__ w2_0, const float* __restrict__ g2_0, const float* __restrict__ b2_0,
    const float* __restrict__ w1_1, const float* __restrict__ g1_1,
    const float* __restrict__ w2_1, const float* __restrict__ g2_1, const float* __restrict__ b2_1)
{
    const int lane = threadIdx.x & 31;
    const int warp = threadIdx.x >> 5;      // 0..11
    const int pairi = warp >> 1;            // 0..5
    const int half = warp & 1;
    const int tid  = threadIdx.x;
    const int o    = half * 32 + lane;      // owned output channel

    __shared__ __align__(16) float hbuf[12][2][64];
    __shared__ int s_chunk;

    int cur_b = -1;
    ull w2r[32];
    float g2o = 0, b2o = 0;
    float g1lo = 0, g1hi = 0;
    float w1x0 = 0, w1y0 = 0, w1z0 = 0, w1x1 = 0, w1y1 = 0, w1z1 = 0;
    const float2* A2 = d_A[0];
    const int*    idxp = d_idx[0];
    const int*    cntp = d_cnt[0];

    for (;;) {
        __syncthreads();
        if (tid == 0) s_chunk = (int)atomicAdd(&d_work, 1u);
        __syncthreads();
        int chunk = s_chunk;
        if (chunk >= NCHUNK) break;

        int b = (chunk >= NCHUNK / 2);
        int gbase = (chunk - b * (NCHUNK / 2)) * 12;

        if (b != cur_b) {
            cur_b = b;
            const float* w1 = b ? w1_1 : w1_0;
            const float* g1 = b ? g1_1 : g1_0;
            const float* w2 = b ? w2_1 : w2_0;
            const float* g2 = b ? g2_1 : g2_0;
            const float* b2 = b ? b2_1 : b2_0;
            const double2* w2d = (const double2*)w2;
#pragma unroll
            for (int jj = 0; jj < 16; jj++) {
                double2 v = w2d[o * 16 + jj];
                w2r[2 * jj] = d2u(v.x); w2r[2 * jj + 1] = d2u(v.y);
            }
            g2o = g2[o]; b2o = b2[o];
            g1lo = g1[lane]; g1hi = g1[lane + 32];
            w1x0 = w1[lane * 131 + 0]; w1y0 = w1[lane * 131 + 1]; w1z0 = w1[lane * 131 + 2];
            w1x1 = w1[(lane + 32) * 131 + 0]; w1y1 = w1[(lane + 32) * 131 + 1]; w1z1 = w1[(lane + 32) * 131 + 2];
            A2 = d_A[b];
            idxp = d_idx[b];
            cntp = d_cnt[b];
        }

        float* hb0 = hbuf[warp][0];
        float* hb1 = hbuf[warp][1];

#pragma unroll 1
        for (int gi = 0; gi < 2; gi++) {
            int g = gbase + pairi * 2 + gi;
            float gx = d_grid[g * 3 + 0], gy = d_grid[g * 3 + 1], gz = d_grid[g * 3 + 2];
            float qlo = g1lo * (w1x0 * gx + w1y0 * gy + w1z0 * gz);
            float qhi = g1hi * (w1x1 * gx + w1y1 * gy + w1z1 * gz);
            int cnt = cntp[g];
            int cm1 = cnt - 1;
            int kreg = idxp[g * NS + (lane & 15)];
            float mx = -1e30f;

            int i1 = (1 < cm1) ? 1 : cm1;
            int i2 = (2 < cm1) ? 2 : cm1;
            int i3 = (3 < cm1) ? 3 : cm1;
            float2 p0 = A2[__shfl_sync(0xffffffffu, kreg, 0)  * 32 + lane];
            float2 p1 = A2[__shfl_sync(0xffffffffu, kreg, i1) * 32 + lane];
            float2 p2 = A2[__shfl_sync(0xffffffffu, kreg, i2) * 32 + lane];
            float2 p3 = A2[__shfl_sync(0xffffffffu, kreg, i3) * 32 + lane];

#pragma unroll 1
            for (int n = 0; n < cnt; n += 2) {
                int j0 = (n + 4 < cnt) ? n + 4 : cm1;
                int j1 = (n + 5 < cnt) ? n + 5 : cm1;
                float2 q0 = A2[__shfl_sync(0xffffffffu, kreg, j0) * 32 + lane];
                float2 q1 = A2[__shfl_sync(0xffffffffu, kreg, j1) * 32 + lane];

                hb0[lane]      = fmaxf(p0.x - qlo, 0.f);
                hb0[lane + 32] = fmaxf(p0.y - qhi, 0.f);
                hb1[lane]      = fmaxf(p1.x - qlo, 0.f);
                hb1[lane + 32] = fmaxf(p1.y - qhi, 0.f);
                __syncwarp();

                ull a0 = 0, a1 = 0;   // sample n
                ull e0 = 0, e1 = 0;   // sample n+1
                const double2* h0 = (const double2*)hb0;
                const double2* h1 = (const double2*)hb1;
#pragma unroll
                for (int jj = 0; jj < 8; jj++) {
                    ull w0 = w2r[4 * jj + 0], w1r = w2r[4 * jj + 1];
                    ull w2_ = w2r[4 * jj + 2], w3 = w2r[4 * jj + 3];
                    double2 v0 = h0[2 * jj], v1 = h0[2 * jj + 1];
                    double2 u0 = h1[2 * jj], u1 = h1[2 * jj + 1];
                    fma2(a0, d2u(v0.x), w0);  fma2(e0, d2u(u0.x), w0);
                    fma2(a1, d2u(v0.y), w1r); fma2(e1, d2u(u0.y), w1r);
                    fma2(a0, d2u(v1.x), w2_); fma2(e0, d2u(u1.x), w2_);
                    fma2(a1, d2u(v1.y), w3);  fma2(e1, d2u(u1.y), w3);
                }
                __syncwarp();

                float2 p, q2;
                p = unpack2(a0); q2 = unpack2(a1);
                mx = fmaxf(mx, fmaf(g2o, (p.x + p.y) + (q2.x + q2.y), b2o));
                p = unpack2(e0); q2 = unpack2(e1);
                mx = fmaxf(mx, fmaf(g2o, (p.x + p.y) + (q2.x + q2.y), b2o));

                p0 = p2; p1 = p3; p2 = q0; p3 = q1;
            }
            int ni = g / N_GRIDP, mi = g % N_GRIDP;
            d_perm[mi * 16384 + (b * 64 + o) * 128 + ni] = fmaxf(mx, 0.f);
        }
    }
}

// ---------------- k5: reduction GEMM layer1, split-K=36, f32x2 ----------------
__global__ void __launch_bounds__(256) k_red1(const float* __restrict__ W)
{
    __shared__ __align__(16) float As[32][132];
    __shared__ __align__(16) float Bs[32][68];
    const int ob = blockIdx.x * 64;
    const int kbase = blockIdx.y * KCHUNK;
    const int tid = threadIdx.x;
    const int tx = tid & 15, ty = tid >> 4;

    ull acc[4][4];
#pragma unroll
    for (int r = 0; r < 4; r++)
#pragma unroll
        for (int c = 0; c < 4; c++) acc[r][c] = 0;

    for (int kc = 0; kc < KCHUNK; kc += 32) {
        int k0 = kbase + kc;
#pragma unroll
        for (int r = 0; r < 16; r++) {
            int e = tid + 256 * r;
            int i = e >> 5, kk = e & 31;
            As[kk][i] = d_perm[i * K_RED + k0 + kk];
        }
#pragma unroll
        for (int r = 0; r < 8; r++) {
            int e = tid + 256 * r;
            int o = e >> 5, kk = e & 31;
            Bs[kk][o] = W[(ob + o) * K_RED + k0 + kk];
        }
        __syncthreads();
#pragma unroll
        for (int kk = 0; kk < 32; kk++) {
            double2 a01 = *(const double2*)&As[kk][ty * 8];
            double2 a23 = *(const double2*)&As[kk][ty * 8 + 4];
            float4 bv = *(const float4*)&Bs[kk][tx * 4];
            ull ap0 = d2u(a01.x), ap1 = d2u(a01.y), ap2 = d2u(a23.x), ap3 = d2u(a23.y);
            ull b0 = splat2(bv.x), b1 = splat2(bv.y), b2 = splat2(bv.z), b3 = splat2(bv.w);
            fma2(acc[0][0], ap0, b0); fma2(acc[0][1], ap0, b1); fma2(acc[0][2], ap0, b2); fma2(acc[0][3], ap0, b3);
            fma2(acc[1][0], ap1, b0); fma2(acc[1][1], ap1, b1); fma2(acc[1][2], ap1, b2); fma2(acc[1][3], ap1, b3);
            fma2(acc[2][0], ap2, b0); fma2(acc[2][1], ap2, b1); fma2(acc[2][2], ap2, b2); fma2(acc[2][3], ap2, b3);
            fma2(acc[3][0], ap3, b0); fma2(acc[3][1], ap3, b1); fma2(acc[3][2], ap3, b2); fma2(acc[3][3], ap3, b3);
        }
        __syncthreads();
    }
    float* outp = d_partial[blockIdx.y];
#pragma unroll
    for (int rp = 0; rp < 4; rp++)
#pragma unroll
        for (int c = 0; c < 4; c++) {
            float2 v = unpack2(acc[rp][c]);
            outp[(ty * 8 + 2 * rp) * 256 + ob + tx * 4 + c] = v.x;
            outp[(ty * 8 + 2 * rp + 1) * 256 + ob + tx * 4 + c] = v.y;
        }
}

// ---------------- k6: partial reduce + bias + relu ----------------
__global__ void k_redfin(const float* __restrict__ b1)
{
    int t = blockIdx.x * 256 + threadIdx.x;
    float s = b1[t & 255];
#pragma unroll
    for (int ks = 0; ks < KSPLIT; ks++) s += d_partial[ks][t];
    d_hbuf[t] = fmaxf(s, 0.f);
}

// ---------------- k6b: transpose W2 ----------------
__global__ void k_w2t(const float* __restrict__ W2)
{
    __shared__ float tbuf[32][33];
    int x = blockIdx.x * 32 + threadIdx.x;
    int y0 = blockIdx.y * 32;
#pragma unroll
    for (int r = threadIdx.y; r < 32; r += 8)
        tbuf[r][threadIdx.x] = W2[(y0 + r) * 256 + x];
    __syncthreads();
    int xo = blockIdx.y * 32 + threadIdx.x;
#pragma unroll
    for (int r = threadIdx.y; r < 32; r += 8)
        d_w2t[(blockIdx.x * 32 + r) * 256 + xo] = tbuf[threadIdx.x][r];
}

// ---------------- k7: layer2 256x256 + relu ----------------
__global__ void __launch_bounds__(256) k_red2(const float* __restrict__ b2, float* __restrict__ out)
{
    __shared__ float hs[256];
    int i = blockIdx.x;
    hs[threadIdx.x] = d_hbuf[i * 256 + threadIdx.x];
    __syncthreads();
    int o = threadIdx.x;
    float s = b2[o];
#pragma unroll 8
    for (int c = 0; c < 256; c++) s = fmaf(hs[c], d_w2t[c * 256 + o], s);
    out[i * 256 + o] = fmaxf(s, 0.f);
}

// ---------------- launch ----------------
extern "C" void kernel_launch(void* const* d_in, const int* in_sizes, int n_in,
                              void* d_out, int out_size)
{
    const float* wlh    = (const float*)d_in[0];
    const float* center = (const float*)d_in[1];
    const float* yaw    = (const float*)d_in[2];
    const float* u      = (const float*)d_in[3];
    const float* kp     = (const float*)d_in[4];
    const float* kf     = (const float*)d_in[5];
    const float* pn0_w1 = (const float*)d_in[6];
    const float* pn0_g1 = (const float*)d_in[7];
    const float* pn0_b1 = (const float*)d_in[8];
    const float* pn0_w2 = (const float*)d_in[9];
    const float* pn0_g2 = (const float*)d_in[10];
    const float* pn0_b2 = (const float*)d_in[11];
    const float* pn1_w1 = (const float*)d_in[12];
    const float* pn1_g1 = (const float*)d_in[13];
    const float* pn1_b1 = (const float*)d_in[14];
    const float* pn1_w2 = (const float*)d_in[15];
    const float* pn1_g2 = (const float*)d_in[16];
    const float* pn1_b2 = (const float*)d_in[17];
    const float* red_w1 = (const float*)d_in[18];
    const float* red_b1 = (const float*)d_in[19];
    const float* red_w2 = (const float*)d_in[20];
    const float* red_b2 = (const float*)d_in[21];
    float* out = (float*)d_out;

    cudaFuncSetAttribute(k_ball, cudaFuncAttributeMaxDynamicSharedMemorySize, 66048);
    cudaFuncSetAttribute(k_A,    cudaFuncAttributeMaxDynamicSharedMemorySize, 32768);

    k_grid<<<(G_TOT + 255) / 256, 256>>>(wlh, center, yaw, u);
    k_ball<<<G_TOT / (BQ_THREADS / 32), BQ_THREADS, 66048>>>(kp);
    k_A<<<dim3(64, 2), dim3(32, 8), 32768>>>(kp, kf, pn0_w1, pn1_w1,
                                             pn0_g1, pn1_g1, pn0_b1, pn1_b1);
    k_branch<<<148, 384>>>(pn0_w1, pn0_g1, pn0_w2, pn0_g2, pn0_b2,
                           pn1_w1, pn1_g1, pn1_w2, pn1_g2, pn1_b2);
    k_w2t<<<dim3(8, 8), dim3(32, 8)>>>(red_w2);
    k_red1<<<dim3(4, KSPLIT), 256>>>(red_w1);
    k_redfin<<<128, 256>>>(red_b1);
    k_red2<<<128, 256>>>(red_b2, out);
}

// round 13
// speedup vs baseline: 1.1037x; 1.1037x over previous
#include <cuda_runtime.h>
#include <cuda_bf16.h>

#define N_PROP 128
#define N_GRIDP 216
#define G_TOT  27648
#define N_KEY  4096
#define C_FEAT 128
#define NS     16
#define K_RED  27648
#define KSPLIT 36
#define KCHUNK 768
#define NCHUNK 3456              // 2 * 27648 / 16
#define BQ_THREADS 512
#define BQ_CHUNKS 1728           // 27648 / 16 warps

typedef unsigned long long ull;

// ---------------- scratch ----------------
static __device__ float  d_grid[G_TOT * 3];
static __device__ float2 d_A[2][N_KEY * 32];    // A' = g1*A + b1, packed (c, c+32)
static __device__ int    d_idx[2][G_TOT * NS];
static __device__ int    d_cnt[2][G_TOT];
static __device__ float  d_perm[N_PROP * K_RED];
static __device__ float  d_partial[KSPLIT][N_PROP * 256];
static __device__ float  d_hbuf[N_PROP * 256];
static __device__ float  d_w2t[256 * 256];
static __device__ unsigned d_work;

// ---------------- f32x2 helpers ----------------
__device__ __forceinline__ ull splat2(float x) {
    ull r;
    asm("mov.b64 %0, {%1, %1};" : "=l"(r) : "f"(x));
    return r;
}
__device__ __forceinline__ void fma2(ull& acc, ull a, ull b) {
    asm("fma.rn.f32x2 %0, %1, %2, %0;" : "+l"(acc) : "l"(a), "l"(b));
}
__device__ __forceinline__ float2 unpack2(ull v) {
    float lo, hi;
    asm("mov.b64 {%0, %1}, %2;" : "=f"(lo), "=f"(hi) : "l"(v));
    return make_float2(lo, hi);
}
__device__ __forceinline__ ull d2u(double d) { return __double_as_longlong(d); }

// ---------------- k1: grid points (+ work counter reset) ----------------
__global__ void k_grid(const float* __restrict__ wlh, const float* __restrict__ center,
                       const float* __restrict__ yaw, const float* __restrict__ u)
{
    if (blockIdx.x == 0 && threadIdx.x == 0) d_work = 0u;
    int g = blockIdx.x * 256 + threadIdx.x;
    if (g >= G_TOT) return;
    int ni = g / N_GRIDP;
    float gx = u[g * 3 + 0] * wlh[ni * 3 + 0];
    float gy = u[g * 3 + 1] * wlh[ni * 3 + 1];
    float gz = u[g * 3 + 2] * wlh[ni * 3 + 2];
    float yv = yaw[ni];
    float c = cosf(yv), s = sinf(yv);
    float rx = c * gx - s * gy;
    float ry = s * gx + c * gy;
    d_grid[g * 3 + 0] = rx + center[ni * 3 + 0];
    d_grid[g * 3 + 1] = ry + center[ni * 3 + 1];
    d_grid[g * 3 + 2] = gz + center[ni * 3 + 2];
}

// ---------------- k2: per-keypoint A' = g1*(kp.w1[:3] + kf.w1[3:]) + b1 -------
__global__ void __launch_bounds__(256) k_A(const float* __restrict__ kp, const float* __restrict__ kf,
                                           const float* __restrict__ w1_0, const float* __restrict__ w1_1,
                                           const float* __restrict__ g1_0, const float* __restrict__ g1_1,
                                           const float* __restrict__ b1_0, const float* __restrict__ b1_1)
{
    __shared__ float w1s[64 * 131];
    extern __shared__ float kfs[];            // 128 c x 64 k = 32 KB dynamic
    const float* w1 = blockIdx.y ? w1_1 : w1_0;
    const float* g1 = blockIdx.y ? g1_1 : g1_0;
    const float* b1 = blockIdx.y ? b1_1 : b1_0;
    int tid = threadIdx.y * 32 + threadIdx.x;
    for (int i = tid; i < 64 * 131; i += 256) w1s[i] = w1[i];

    int kbase = blockIdx.x * 64;
    for (int e = tid; e < C_FEAT * 64; e += 256) {
        int c = e >> 6, kk = e & 63;
        kfs[c * 64 + kk] = kf[c * N_KEY + kbase + kk];
    }
    __syncthreads();

    int l = threadIdx.x;
    float g1lo = g1[l], g1hi = g1[l + 32];
    float b1lo = b1[l], b1hi = b1[l + 32];
#pragma unroll 1
    for (int t = 0; t < 8; t++) {
        int kk = t * 8 + threadIdx.y;
        int k = kbase + kk;
        float kx = kp[k * 3 + 0], ky = kp[k * 3 + 1], kz = kp[k * 3 + 2];
        float a0 = w1s[l * 131 + 0] * kx + w1s[l * 131 + 1] * ky + w1s[l * 131 + 2] * kz;
        float a1 = w1s[(l + 32) * 131 + 0] * kx + w1s[(l + 32) * 131 + 1] * ky + w1s[(l + 32) * 131 + 2] * kz;
#pragma unroll 4
        for (int c = 0; c < C_FEAT; c++) {
            float f = kfs[c * 64 + kk];
            a0 = fmaf(f, w1s[l * 131 + 3 + c], a0);
            a1 = fmaf(f, w1s[(l + 32) * 131 + 3 + c], a1);
        }
        d_A[blockIdx.y][k * 32 + l] = make_float2(fmaf(g1lo, a0, b1lo), fmaf(g1hi, a1, b1hi));
    }
}

// ---------------- k3: warp-cooperative ball query, PERSISTENT ----------------
__device__ __forceinline__ void bq_merge(int* __restrict__ out, int* __restrict__ cntout,
                                         int c, const int* h, int lane)
{
    const unsigned full = 0xffffffffu;
    int pre = c;
#pragma unroll
    for (int off = 1; off < 32; off <<= 1) {
        int t = __shfl_up_sync(full, pre, off);
        if (lane >= off) pre += t;
    }
    int excl = pre - c;
    int total = __shfl_sync(full, pre, 31);
    unsigned ball = __ballot_sync(full, c > 0);
    int myfirst = lane * 128 + h[0];
    int fl = (ball != 0u) ? (__ffs(ball) - 1) : 0;
    int f = __shfl_sync(full, myfirst, fl);
    if (ball == 0u) f = 0;
#pragma unroll 1
    for (int t = 0; t < c; t++) {
        int pos = excl + t;
        if (pos < NS) out[pos] = lane * 128 + h[t];
    }
    int tot16 = (total < NS) ? total : NS;
    for (int p = tot16 + lane; p < NS; p += 32) out[p] = f;
    if (lane == 0) *cntout = (tot16 > 0) ? tot16 : 1;
}

__global__ void __launch_bounds__(BQ_THREADS) k_ball(const float* __restrict__ kp)
{
    extern __shared__ float4 kpt[];   // [lane*129 + i], 4128 float4 = 66048 B
    int tid = threadIdx.x;
    for (int k = tid; k < N_KEY; k += BQ_THREADS) {
        int l = k >> 7, i = k & 127;
        float kx = kp[k * 3 + 0], ky = kp[k * 3 + 1], kz = kp[k * 3 + 2];
        kpt[l * 129 + i] = make_float4(kx, ky, kz, kx * kx + ky * ky + kz * kz);
    }
    __syncthreads();

    int lane = tid & 31, warp = tid >> 5;
    const float4* my = kpt + lane * 129;

#pragma unroll 1
    for (int t = blockIdx.x; t < BQ_CHUNKS; t += 148) {
        int g = t * (BQ_THREADS / 32) + warp;

        float gx = d_grid[g * 3 + 0], gy = d_grid[g * 3 + 1], gz = d_grid[g * 3 + 2];
        float gs = gx * gx + gy * gy + gz * gz;
        float m2x = -2.f * gx, m2y = -2.f * gy, m2z = -2.f * gz;

        int h0[NS], h1[NS];
        h0[0] = 0; h1[0] = 0;
        int c0 = 0, c1 = 0;

#pragma unroll 1
        for (int i = 0; i < 128; i += 4) {
            float4 v0 = my[i + 0];
            float4 v1 = my[i + 1];
            float4 v2 = my[i + 2];
            float4 v3 = my[i + 3];
            float d20 = fmaf(m2x, v0.x, fmaf(m2y, v0.y, fmaf(m2z, v0.z, gs + v0.w)));
            float d21 = fmaf(m2x, v1.x, fmaf(m2y, v1.y, fmaf(m2z, v1.z, gs + v1.w)));
            float d22 = fmaf(m2x, v2.x, fmaf(m2y, v2.y, fmaf(m2z, v2.z, gs + v2.w)));
            float d23 = fmaf(m2x, v3.x, fmaf(m2y, v3.y, fmaf(m2z, v3.z, gs + v3.w)));
            if (fminf(fminf(d20, d21), fminf(d22, d23)) < 2.56f) {   // rare
                if (d20 < 2.56f) { if (c1 < NS) h1[c1++] = i + 0; if (d20 < 0.64f && c0 < NS) h0[c0++] = i + 0; }
                if (d21 < 2.56f) { if (c1 < NS) h1[c1++] = i + 1; if (d21 < 0.64f && c0 < NS) h0[c0++] = i + 1; }
                if (d22 < 2.56f) { if (c1 < NS) h1[c1++] = i + 2; if (d22 < 0.64f && c0 < NS) h0[c0++] = i + 2; }
                if (d23 < 2.56f) { if (c1 < NS) h1[c1++] = i + 3; if (d23 < 0.64f && c0 < NS) h0[c0++] = i + 3; }
            }
        }
        bq_merge(&d_idx[0][g * NS], &d_cnt[0][g], c0, h0, lane);
        bq_merge(&d_idx[1][g * NS], &d_cnt[1][g], c1, h1, lane);
    }
}

// ---------------- k4: branch MLP + maxpool (R9 shape + A' folding) ------------
// warp per gridpoint, lane owns channels (lane, lane+32), 2 samples/iter.
__global__ void __launch_bounds__(256, 1) k_branch(
    const float* __restrict__ w1_0, const float* __restrict__ g1_0,
    const float* __restrict__ w2_0, const float* __restrict__ g2_0, const float* __restrict__ b2_0,
    const float* __restrict__ w1_1, const float* __restrict__ g1_1,
    const float* __restrict__ w2_1, const float* __restrict__ g2_1, const float* __restrict__ b2_1)
{
    const int lane = threadIdx.x & 31;
    const int warp = threadIdx.x >> 5;
    const int tid  = threadIdx.x;

    __shared__ __align__(16) float hbuf[8][4][64];
    __shared__ int s_chunk;

    int cur_b = -1;
    ull w2lo[32], w2hi[32];
    float g2lo = 0, g2hi = 0, b2lo = 0, b2hi = 0;
    float g1lo = 0, g1hi = 0;
    float w1x0 = 0, w1y0 = 0, w1z0 = 0, w1x1 = 0, w1y1 = 0, w1z1 = 0;
    const float2* A2 = d_A[0];
    const int*    idxp = d_idx[0];
    const int*    cntp = d_cnt[0];

    for (;;) {
        __syncthreads();
        if (tid == 0) s_chunk = (int)atomicAdd(&d_work, 1u);
        __syncthreads();
        int chunk = s_chunk;
        if (chunk >= NCHUNK) break;

        int b = (chunk >= NCHUNK / 2);
        int gbase = (chunk - b * (NCHUNK / 2)) * 16;

        if (b != cur_b) {
            cur_b = b;
            const float* w1 = b ? w1_1 : w1_0;
            const float* g1 = b ? g1_1 : g1_0;
            const float* w2 = b ? w2_1 : w2_0;
            const float* g2 = b ? g2_1 : g2_0;
            const float* b2 = b ? b2_1 : b2_0;
            const double2* w2d = (const double2*)w2;
#pragma unroll
            for (int jj = 0; jj < 16; jj++) {
                double2 vlo = w2d[lane * 16 + jj];
                double2 vhi = w2d[(lane + 32) * 16 + jj];
                w2lo[2 * jj] = d2u(vlo.x); w2lo[2 * jj + 1] = d2u(vlo.y);
                w2hi[2 * jj] = d2u(vhi.x); w2hi[2 * jj + 1] = d2u(vhi.y);
            }
            g2lo = g2[lane]; g2hi = g2[lane + 32];
            b2lo = b2[lane]; b2hi = b2[lane + 32];
            g1lo = g1[lane]; g1hi = g1[lane + 32];
            w1x0 = w1[lane * 131 + 0]; w1y0 = w1[lane * 131 + 1]; w1z0 = w1[lane * 131 + 2];
            w1x1 = w1[(lane + 32) * 131 + 0]; w1y1 = w1[(lane + 32) * 131 + 1]; w1z1 = w1[(lane + 32) * 131 + 2];
            A2 = d_A[b];
            idxp = d_idx[b];
            cntp = d_cnt[b];
        }

#pragma unroll 1
        for (int gi = 0; gi < 2; gi++) {
            int g = gbase + warp * 2 + gi;
            float gx = d_grid[g * 3 + 0], gy = d_grid[g * 3 + 1], gz = d_grid[g * 3 + 2];
            float qlo = g1lo * (w1x0 * gx + w1y0 * gy + w1z0 * gz);
            float qhi = g1hi * (w1x1 * gx + w1y1 * gy + w1z1 * gz);
            int cnt = cntp[g];
            int cm1 = cnt - 1;
            int kreg = idxp[g * NS + (lane & 15)];
            float mxA = -1e30f, mxB = -1e30f;

            int i1 = (1 < cm1) ? 1 : cm1;
            int i2 = (2 < cm1) ? 2 : cm1;
            int i3 = (3 < cm1) ? 3 : cm1;
            float2 p0 = A2[__shfl_sync(0xffffffffu, kreg, 0)  * 32 + lane];
            float2 p1 = A2[__shfl_sync(0xffffffffu, kreg, i1) * 32 + lane];
            float2 p2 = A2[__shfl_sync(0xffffffffu, kreg, i2) * 32 + lane];
            float2 p3 = A2[__shfl_sync(0xffffffffu, kreg, i3) * 32 + lane];

#pragma unroll 1
            for (int n = 0; n < cnt; n += 2) {
                int j0 = (n + 4 < cnt) ? n + 4 : cm1;
                int j1 = (n + 5 < cnt) ? n + 5 : cm1;
                float2 q0 = A2[__shfl_sync(0xffffffffu, kreg, j0) * 32 + lane];
                float2 q1 = A2[__shfl_sync(0xffffffffu, kreg, j1) * 32 + lane];

                float* hb0 = hbuf[warp][((n >> 1) & 1) * 2 + 0];
                float* hb1 = hbuf[warp][((n >> 1) & 1) * 2 + 1];
                hb0[lane]      = fmaxf(p0.x - qlo, 0.f);
                hb0[lane + 32] = fmaxf(p0.y - qhi, 0.f);
                hb1[lane]      = fmaxf(p1.x - qlo, 0.f);
                hb1[lane + 32] = fmaxf(p1.y - qhi, 0.f);
                __syncwarp();

                ull a0 = 0, a1 = 0, c0 = 0, c1 = 0;      // sample n
                ull e0 = 0, e1 = 0, f0 = 0, f1 = 0;      // sample n+1
                const double2* h0 = (const double2*)hb0;
                const double2* h1 = (const double2*)hb1;
#pragma unroll
                for (int jj = 0; jj < 8; jj++) {
                    ull wl0 = w2lo[4 * jj + 0], wl1 = w2lo[4 * jj + 1];
                    ull wl2 = w2lo[4 * jj + 2], wl3 = w2lo[4 * jj + 3];
                    ull wh0 = w2hi[4 * jj + 0], wh1 = w2hi[4 * jj + 1];
                    ull wh2 = w2hi[4 * jj + 2], wh3 = w2hi[4 * jj + 3];
                    double2 v0 = h0[2 * jj], v1 = h0[2 * jj + 1];
                    double2 u0 = h1[2 * jj], u1 = h1[2 * jj + 1];
                    fma2(a0, d2u(v0.x), wl0); fma2(e0, d2u(u0.x), wl0);
                    fma2(a1, d2u(v0.y), wl1); fma2(e1, d2u(u0.y), wl1);
                    fma2(c0, d2u(v0.x), wh0); fma2(f0, d2u(u0.x), wh0);
                    fma2(c1, d2u(v0.y), wh1); fma2(f1, d2u(u0.y), wh1);
                    fma2(a0, d2u(v1.x), wl2); fma2(e0, d2u(u1.x), wl2);
                    fma2(a1, d2u(v1.y), wl3); fma2(e1, d2u(u1.y), wl3);
                    fma2(c0, d2u(v1.x), wh2); fma2(f0, d2u(u1.x), wh2);
                    fma2(c1, d2u(v1.y), wh3); fma2(f1, d2u(u1.y), wh3);
                }

                float2 p, q2;
                p = unpack2(a0); q2 = unpack2(a1);
                mxA = fmaxf(mxA, fmaf(g2lo, (p.x + p.y) + (q2.x + q2.y), b2lo));
                p = unpack2(c0); q2 = unpack2(c1);
                mxB = fmaxf(mxB, fmaf(g2hi, (p.x + p.y) + (q2.x + q2.y), b2hi));
                p = unpack2(e0); q2 = unpack2(e1);
                mxA = fmaxf(mxA, fmaf(g2lo, (p.x + p.y) + (q2.x + q2.y), b2lo));
                p = unpack2(f0); q2 = unpack2(f1);
                mxB = fmaxf(mxB, fmaf(g2hi, (p.x + p.y) + (q2.x + q2.y), b2hi));

                p0 = p2; p1 = p3; p2 = q0; p3 = q1;
            }
            int ni = g / N_GRIDP, mi = g % N_GRIDP;
            int cpA = b * 64 + lane;
            d_perm[mi * 16384 + cpA * 128 + ni] = fmaxf(mxA, 0.f);
            d_perm[mi * 16384 + (cpA + 32) * 128 + ni] = fmaxf(mxB, 0.f);
        }
    }
}

// ---------------- k5: reduction GEMM layer1, split-K=36, f32x2 ----------------
__global__ void __launch_bounds__(256) k_red1(const float* __restrict__ W)
{
    __shared__ __align__(16) float As[32][132];
    __shared__ __align__(16) float Bs[32][68];
    const int ob = blockIdx.x * 64;
    const int kbase = blockIdx.y * KCHUNK;
    const int tid = threadIdx.x;
    const int tx = tid & 15, ty = tid >> 4;

    ull acc[4][4];
#pragma unroll
    for (int r = 0; r < 4; r++)
#pragma unroll
        for (int c = 0; c < 4; c++) acc[r][c] = 0;

    for (int kc = 0; kc < KCHUNK; kc += 32) {
        int k0 = kbase + kc;
#pragma unroll
        for (int r = 0; r < 16; r++) {
            int e = tid + 256 * r;
            int i = e >> 5, kk = e & 31;
            As[kk][i] = d_perm[i * K_RED + k0 + kk];
        }
#pragma unroll
        for (int r = 0; r < 8; r++) {
            int e = tid + 256 * r;
            int o = e >> 5, kk = e & 31;
            Bs[kk][o] = W[(ob + o) * K_RED + k0 + kk];
        }
        __syncthreads();
#pragma unroll
        for (int kk = 0; kk < 32; kk++) {
            double2 a01 = *(const double2*)&As[kk][ty * 8];
            double2 a23 = *(const double2*)&As[kk][ty * 8 + 4];
            float4 bv = *(const float4*)&Bs[kk][tx * 4];
            ull ap0 = d2u(a01.x), ap1 = d2u(a01.y), ap2 = d2u(a23.x), ap3 = d2u(a23.y);
            ull b0 = splat2(bv.x), b1 = splat2(bv.y), b2 = splat2(bv.z), b3 = splat2(bv.w);
            fma2(acc[0][0], ap0, b0); fma2(acc[0][1], ap0, b1); fma2(acc[0][2], ap0, b2); fma2(acc[0][3], ap0, b3);
            fma2(acc[1][0], ap1, b0); fma2(acc[1][1], ap1, b1); fma2(acc[1][2], ap1, b2); fma2(acc[1][3], ap1, b3);
            fma2(acc[2][0], ap2, b0); fma2(acc[2][1], ap2, b1); fma2(acc[2][2], ap2, b2); fma2(acc[2][3], ap2, b3);
            fma2(acc[3][0], ap3, b0); fma2(acc[3][1], ap3, b1); fma2(acc[3][2], ap3, b2); fma2(acc[3][3], ap3, b3);
        }
        __syncthreads();
    }
    float* outp = d_partial[blockIdx.y];
#pragma unroll
    for (int rp = 0; rp < 4; rp++)
#pragma unroll
        for (int c = 0; c < 4; c++) {
            float2 v = unpack2(acc[rp][c]);
            outp[(ty * 8 + 2 * rp) * 256 + ob + tx * 4 + c] = v.x;
            outp[(ty * 8 + 2 * rp + 1) * 256 + ob + tx * 4 + c] = v.y;
        }
}

// ---------------- k6: partial reduce + bias + relu ----------------
__global__ void k_redfin(const float* __restrict__ b1)
{
    int t = blockIdx.x * 256 + threadIdx.x;
    float s = b1[t & 255];
#pragma unroll
    for (int ks = 0; ks < KSPLIT; ks++) s += d_partial[ks][t];
    d_hbuf[t] = fmaxf(s, 0.f);
}

// ---------------- k6b: transpose W2 ----------------
__global__ void k_w2t(const float* __restrict__ W2)
{
    __shared__ float tbuf[32][33];
    int x = blockIdx.x * 32 + threadIdx.x;
    int y0 = blockIdx.y * 32;
#pragma unroll
    for (int r = threadIdx.y; r < 32; r += 8)
        tbuf[r][threadIdx.x] = W2[(y0 + r) * 256 + x];
    __syncthreads();
    int xo = blockIdx.y * 32 + threadIdx.x;
#pragma unroll
    for (int r = threadIdx.y; r < 32; r += 8)
        d_w2t[(blockIdx.x * 32 + r) * 256 + xo] = tbuf[threadIdx.x][r];
}

// ---------------- k7: layer2 256x256 + relu ----------------
__global__ void __launch_bounds__(256) k_red2(const float* __restrict__ b2, float* __restrict__ out)
{
    __shared__ float hs[256];
    int i = blockIdx.x;
    hs[threadIdx.x] = d_hbuf[i * 256 + threadIdx.x];
    __syncthreads();
    int o = threadIdx.x;
    float s = b2[o];
#pragma unroll 8
    for (int c = 0; c < 256; c++) s = fmaf(hs[c], d_w2t[c * 256 + o], s);
    out[i * 256 + o] = fmaxf(s, 0.f);
}

// ---------------- launch ----------------
extern "C" void kernel_launch(void* const* d_in, const int* in_sizes, int n_in,
                              void* d_out, int out_size)
{
    const float* wlh    = (const float*)d_in[0];
    const float* center = (const float*)d_in[1];
    const float* yaw    = (const float*)d_in[2];
    const float* u      = (const float*)d_in[3];
    const float* kp     = (const float*)d_in[4];
    const float* kf     = (const float*)d_in[5];
    const float* pn0_w1 = (const float*)d_in[6];
    const float* pn0_g1 = (const float*)d_in[7];
    const float* pn0_b1 = (const float*)d_in[8];
    const float* pn0_w2 = (const float*)d_in[9];
    const float* pn0_g2 = (const float*)d_in[10];
    const float* pn0_b2 = (const float*)d_in[11];
    const float* pn1_w1 = (const float*)d_in[12];
    const float* pn1_g1 = (const float*)d_in[13];
    const float* pn1_b1 = (const float*)d_in[14];
    const float* pn1_w2 = (const float*)d_in[15];
    const float* pn1_g2 = (const float*)d_in[16];
    const float* pn1_b2 = (const float*)d_in[17];
    const float* red_w1 = (const float*)d_in[18];
    const float* red_b1 = (const float*)d_in[19];
    const float* red_w2 = (const float*)d_in[20];
    const float* red_b2 = (const float*)d_in[21];
    float* out = (float*)d_out;

    cudaFuncSetAttribute(k_ball, cudaFuncAttributeMaxDynamicSharedMemorySize, 66048);
    cudaFuncSetAttribute(k_A,    cudaFuncAttributeMaxDynamicSharedMemorySize, 32768);

    k_grid<<<(G_TOT + 255) / 256, 256>>>(wlh, center, yaw, u);
    k_ball<<<148, BQ_THREADS, 66048>>>(kp);
    k_A<<<dim3(64, 2), dim3(32, 8), 32768>>>(kp, kf, pn0_w1, pn1_w1,
                                             pn0_g1, pn1_g1, pn0_b1, pn1_b1);
    k_branch<<<148, 256>>>(pn0_w1, pn0_g1, pn0_w2, pn0_g2, pn0_b2,
                           pn1_w1, pn1_g1, pn1_w2, pn1_g2, pn1_b2);
    k_w2t<<<dim3(8, 8), dim3(32, 8)>>>(red_w2);
    k_red1<<<dim3(4, KSPLIT), 256>>>(red_w1);
    k_redfin<<<128, 256>>>(red_b1);
    k_red2<<<128, 256>>>(red_b2, out);
}

// round 14
// speedup vs baseline: 1.1283x; 1.0223x over previous
#include <cuda_runtime.h>
#include <cuda_bf16.h>

#define N_PROP 128
#define N_GRIDP 216
#define G_TOT  27648
#define N_KEY  4096
#define C_FEAT 128
#define NS     16
#define K_RED  27648
#define KSPLIT 72
#define KCHUNK 384
#define NCHUNK 3456              // 2 * 27648 / 16
#define BQ_THREADS 512
#define BQ_CHUNKS 1728

typedef unsigned long long ull;

// ---------------- scratch ----------------
static __device__ float  d_grid[G_TOT * 3];
static __device__ float2 d_A[2][N_KEY * 32];    // A' = g1*A + b1, packed (c, c+32)
static __device__ int    d_idx[2][G_TOT * NS];
static __device__ int    d_cnt[2][G_TOT];
static __device__ float  d_perm[N_PROP * K_RED];
static __device__ float  d_partial[KSPLIT][N_PROP * 256];
static __device__ float  d_hbuf[N_PROP * 256];
static __device__ float  d_w2t[256 * 256];
static __device__ unsigned d_work;

// ---------------- f32x2 helpers ----------------
__device__ __forceinline__ ull splat2(float x) {
    ull r;
    asm("mov.b64 %0, {%1, %1};" : "=l"(r) : "f"(x));
    return r;
}
__device__ __forceinline__ void fma2(ull& acc, ull a, ull b) {
    asm("fma.rn.f32x2 %0, %1, %2, %0;" : "+l"(acc) : "l"(a), "l"(b));
}
__device__ __forceinline__ float2 unpack2(ull v) {
    float lo, hi;
    asm("mov.b64 {%0, %1}, %2;" : "=f"(lo), "=f"(hi) : "l"(v));
    return make_float2(lo, hi);
}
__device__ __forceinline__ ull d2u(double d) { return __double_as_longlong(d); }

// ---------------- k1: grid points (+ work counter reset) ----------------
__global__ void k_grid(const float* __restrict__ wlh, const float* __restrict__ center,
                       const float* __restrict__ yaw, const float* __restrict__ u)
{
    if (blockIdx.x == 0 && threadIdx.x == 0) d_work = 0u;
    int g = blockIdx.x * 256 + threadIdx.x;
    if (g >= G_TOT) return;
    int ni = g / N_GRIDP;
    float gx = u[g * 3 + 0] * wlh[ni * 3 + 0];
    float gy = u[g * 3 + 1] * wlh[ni * 3 + 1];
    float gz = u[g * 3 + 2] * wlh[ni * 3 + 2];
    float yv = yaw[ni];
    float c = cosf(yv), s = sinf(yv);
    float rx = c * gx - s * gy;
    float ry = s * gx + c * gy;
    d_grid[g * 3 + 0] = rx + center[ni * 3 + 0];
    d_grid[g * 3 + 1] = ry + center[ni * 3 + 1];
    d_grid[g * 3 + 2] = gz + center[ni * 3 + 2];
}

// ---------------- k2: per-keypoint A' = g1*(kp.w1[:3] + kf.w1[3:]) + b1 -------
__global__ void __launch_bounds__(256) k_A(const float* __restrict__ kp, const float* __restrict__ kf,
                                           const float* __restrict__ w1_0, const float* __restrict__ w1_1,
                                           const float* __restrict__ g1_0, const float* __restrict__ g1_1,
                                           const float* __restrict__ b1_0, const float* __restrict__ b1_1)
{
    __shared__ float w1s[64 * 131];
    extern __shared__ float kfs[];            // 128 c x 64 k = 32 KB dynamic
    const float* w1 = blockIdx.y ? w1_1 : w1_0;
    const float* g1 = blockIdx.y ? g1_1 : g1_0;
    const float* b1 = blockIdx.y ? b1_1 : b1_0;
    int tid = threadIdx.y * 32 + threadIdx.x;
    for (int i = tid; i < 64 * 131; i += 256) w1s[i] = w1[i];

    int kbase = blockIdx.x * 64;
    for (int e = tid; e < C_FEAT * 64; e += 256) {
        int c = e >> 6, kk = e & 63;
        kfs[c * 64 + kk] = kf[c * N_KEY + kbase + kk];
    }
    __syncthreads();

    int l = threadIdx.x;
    float g1lo = g1[l], g1hi = g1[l + 32];
    float b1lo = b1[l], b1hi = b1[l + 32];
#pragma unroll 1
    for (int t = 0; t < 8; t++) {
        int kk = t * 8 + threadIdx.y;
        int k = kbase + kk;
        float kx = kp[k * 3 + 0], ky = kp[k * 3 + 1], kz = kp[k * 3 + 2];
        float a0 = w1s[l * 131 + 0] * kx + w1s[l * 131 + 1] * ky + w1s[l * 131 + 2] * kz;
        float a1 = w1s[(l + 32) * 131 + 0] * kx + w1s[(l + 32) * 131 + 1] * ky + w1s[(l + 32) * 131 + 2] * kz;
#pragma unroll 4
        for (int c = 0; c < C_FEAT; c++) {
            float f = kfs[c * 64 + kk];
            a0 = fmaf(f, w1s[l * 131 + 3 + c], a0);
            a1 = fmaf(f, w1s[(l + 32) * 131 + 3 + c], a1);
        }
        d_A[blockIdx.y][k * 32 + l] = make_float2(fmaf(g1lo, a0, b1lo), fmaf(g1hi, a1, b1hi));
    }
}

// ---------------- k3: warp-cooperative ball query, PERSISTENT ----------------
__device__ __forceinline__ void bq_merge(int* __restrict__ out, int* __restrict__ cntout,
                                         int c, const int* h, int lane)
{
    const unsigned full = 0xffffffffu;
    int pre = c;
#pragma unroll
    for (int off = 1; off < 32; off <<= 1) {
        int t = __shfl_up_sync(full, pre, off);
        if (lane >= off) pre += t;
    }
    int excl = pre - c;
    int total = __shfl_sync(full, pre, 31);
    unsigned ball = __ballot_sync(full, c > 0);
    int myfirst = lane * 128 + h[0];
    int fl = (ball != 0u) ? (__ffs(ball) - 1) : 0;
    int f = __shfl_sync(full, myfirst, fl);
    if (ball == 0u) f = 0;
#pragma unroll 1
    for (int t = 0; t < c; t++) {
        int pos = excl + t;
        if (pos < NS) out[pos] = lane * 128 + h[t];
    }
    int tot16 = (total < NS) ? total : NS;
    for (int p = tot16 + lane; p < NS; p += 32) out[p] = f;
    if (lane == 0) *cntout = (tot16 > 0) ? tot16 : 1;
}

__global__ void __launch_bounds__(BQ_THREADS) k_ball(const float* __restrict__ kp)
{
    extern __shared__ float4 kpt[];   // [lane*129 + i], 4128 float4 = 66048 B
    int tid = threadIdx.x;
    for (int k = tid; k < N_KEY; k += BQ_THREADS) {
        int l = k >> 7, i = k & 127;
        float kx = kp[k * 3 + 0], ky = kp[k * 3 + 1], kz = kp[k * 3 + 2];
        kpt[l * 129 + i] = make_float4(kx, ky, kz, kx * kx + ky * ky + kz * kz);
    }
    __syncthreads();

    int lane = tid & 31, warp = tid >> 5;
    const float4* my = kpt + lane * 129;

#pragma unroll 1
    for (int t = blockIdx.x; t < BQ_CHUNKS; t += 148) {
        int g = t * (BQ_THREADS / 32) + warp;

        float gx = d_grid[g * 3 + 0], gy = d_grid[g * 3 + 1], gz = d_grid[g * 3 + 2];
        float gs = gx * gx + gy * gy + gz * gz;
        float m2x = -2.f * gx, m2y = -2.f * gy, m2z = -2.f * gz;

        int h0[NS], h1[NS];
        h0[0] = 0; h1[0] = 0;
        int c0 = 0, c1 = 0;

#pragma unroll 1
        for (int i = 0; i < 128; i += 4) {
            float4 v0 = my[i + 0];
            float4 v1 = my[i + 1];
            float4 v2 = my[i + 2];
            float4 v3 = my[i + 3];
            float d20 = fmaf(m2x, v0.x, fmaf(m2y, v0.y, fmaf(m2z, v0.z, gs + v0.w)));
            float d21 = fmaf(m2x, v1.x, fmaf(m2y, v1.y, fmaf(m2z, v1.z, gs + v1.w)));
            float d22 = fmaf(m2x, v2.x, fmaf(m2y, v2.y, fmaf(m2z, v2.z, gs + v2.w)));
            float d23 = fmaf(m2x, v3.x, fmaf(m2y, v3.y, fmaf(m2z, v3.z, gs + v3.w)));
            if (fminf(fminf(d20, d21), fminf(d22, d23)) < 2.56f) {   // rare
                if (d20 < 2.56f) { if (c1 < NS) h1[c1++] = i + 0; if (d20 < 0.64f && c0 < NS) h0[c0++] = i + 0; }
                if (d21 < 2.56f) { if (c1 < NS) h1[c1++] = i + 1; if (d21 < 0.64f && c0 < NS) h0[c0++] = i + 1; }
                if (d22 < 2.56f) { if (c1 < NS) h1[c1++] = i + 2; if (d22 < 0.64f && c0 < NS) h0[c0++] = i + 2; }
                if (d23 < 2.56f) { if (c1 < NS) h1[c1++] = i + 3; if (d23 < 0.64f && c0 < NS) h0[c0++] = i + 3; }
            }
        }
        bq_merge(&d_idx[0][g * NS], &d_cnt[0][g], c0, h0, lane);
        bq_merge(&d_idx[1][g * NS], &d_cnt[1][g], c1, h1, lane);
    }
}

// ---------------- k4: branch MLP + maxpool, w2 in smem, 4 samples/iter --------
// warp per gridpoint, lane owns channels (lane, lane+32).
// w2 stored [b][c/4][o][4] -> per-jj LDS.128, lanes contiguous = conflict-free.
// 2 CTAs/SM forced (<=128 regs) -> 16 warps/SM.
__global__ void __launch_bounds__(256, 2) k_branch(
    const float* __restrict__ w1_0, const float* __restrict__ g1_0,
    const float* __restrict__ w2_0, const float* __restrict__ g2_0, const float* __restrict__ b2_0,
    const float* __restrict__ w1_1, const float* __restrict__ g1_1,
    const float* __restrict__ w2_1, const float* __restrict__ g2_1, const float* __restrict__ b2_1)
{
    const int lane = threadIdx.x & 31;
    const int warp = threadIdx.x >> 5;
    const int tid  = threadIdx.x;

    __shared__ __align__(16) float w2s[2][16][64][4];   // 32 KB, both branches
    __shared__ __align__(16) float hbuf[8][4][64];      // 8 KB, 4 samples/warp
    __shared__ int s_chunk;

    // fill w2s once (visible after first chunk-loop barrier)
    for (int e = tid; e < 2 * 64 * 64; e += 256) {
        int b = e >> 12, r = e & 4095, o = r >> 6, c = r & 63;
        const float* w2 = b ? w2_1 : w2_0;
        w2s[b][c >> 2][o][c & 3] = w2[o * 64 + c];
    }

    int cur_b = -1;
    float g2lo = 0, g2hi = 0, b2lo = 0, b2hi = 0;
    float g1lo = 0, g1hi = 0;
    float w1x0 = 0, w1y0 = 0, w1z0 = 0, w1x1 = 0, w1y1 = 0, w1z1 = 0;
    const float2* A2 = d_A[0];
    const int*    idxp = d_idx[0];
    const int*    cntp = d_cnt[0];

    for (;;) {
        __syncthreads();
        if (tid == 0) s_chunk = (int)atomicAdd(&d_work, 1u);
        __syncthreads();
        int chunk = s_chunk;
        if (chunk >= NCHUNK) break;

        int b = (chunk >= NCHUNK / 2);
        int gbase = (chunk - b * (NCHUNK / 2)) * 16;

        if (b != cur_b) {
            cur_b = b;
            const float* w1 = b ? w1_1 : w1_0;
            const float* g1 = b ? g1_1 : g1_0;
            const float* g2 = b ? g2_1 : g2_0;
            const float* b2 = b ? b2_1 : b2_0;
            g2lo = g2[lane]; g2hi = g2[lane + 32];
            b2lo = b2[lane]; b2hi = b2[lane + 32];
            g1lo = g1[lane]; g1hi = g1[lane + 32];
            w1x0 = w1[lane * 131 + 0]; w1y0 = w1[lane * 131 + 1]; w1z0 = w1[lane * 131 + 2];
            w1x1 = w1[(lane + 32) * 131 + 0]; w1y1 = w1[(lane + 32) * 131 + 1]; w1z1 = w1[(lane + 32) * 131 + 2];
            A2 = d_A[b];
            idxp = d_idx[b];
            cntp = d_cnt[b];
        }

        const float (*w2b)[64][4] = w2s[b];
        float* hb = &hbuf[warp][0][0];

#pragma unroll 1
        for (int gi = 0; gi < 2; gi++) {
            int g = gbase + warp * 2 + gi;
            float gx = d_grid[g * 3 + 0], gy = d_grid[g * 3 + 1], gz = d_grid[g * 3 + 2];
            float qlo = g1lo * (w1x0 * gx + w1y0 * gy + w1z0 * gz);
            float qhi = g1hi * (w1x1 * gx + w1y1 * gy + w1z1 * gz);
            int cnt = cntp[g];
            int cm1 = cnt - 1;
            int kreg = idxp[g * NS + (lane & 15)];
            float mxA = -1e30f, mxB = -1e30f;

            // prologue: 4 samples (clamped dup indices are idempotent under max)
            int i1 = (1 < cm1) ? 1 : cm1;
            int i2 = (2 < cm1) ? 2 : cm1;
            int i3 = (3 < cm1) ? 3 : cm1;
            float2 p0 = A2[__shfl_sync(0xffffffffu, kreg, 0)  * 32 + lane];
            float2 p1 = A2[__shfl_sync(0xffffffffu, kreg, i1) * 32 + lane];
            float2 p2 = A2[__shfl_sync(0xffffffffu, kreg, i2) * 32 + lane];
            float2 p3 = A2[__shfl_sync(0xffffffffu, kreg, i3) * 32 + lane];

#pragma unroll 1
            for (int n = 0; n < cnt; n += 4) {
                int j0 = (n + 4 < cnt) ? n + 4 : cm1;
                int j1 = (n + 5 < cnt) ? n + 5 : cm1;
                int j2 = (n + 6 < cnt) ? n + 6 : cm1;
                int j3 = (n + 7 < cnt) ? n + 7 : cm1;
                float2 q0 = A2[__shfl_sync(0xffffffffu, kreg, j0) * 32 + lane];
                float2 q1 = A2[__shfl_sync(0xffffffffu, kreg, j1) * 32 + lane];
                float2 q2v = A2[__shfl_sync(0xffffffffu, kreg, j2) * 32 + lane];
                float2 q3 = A2[__shfl_sync(0xffffffffu, kreg, j3) * 32 + lane];

                hb[0 * 64 + lane]      = fmaxf(p0.x - qlo, 0.f);
                hb[0 * 64 + lane + 32] = fmaxf(p0.y - qhi, 0.f);
                hb[1 * 64 + lane]      = fmaxf(p1.x - qlo, 0.f);
                hb[1 * 64 + lane + 32] = fmaxf(p1.y - qhi, 0.f);
                hb[2 * 64 + lane]      = fmaxf(p2.x - qlo, 0.f);
                hb[2 * 64 + lane + 32] = fmaxf(p2.y - qhi, 0.f);
                hb[3 * 64 + lane]      = fmaxf(p3.x - qlo, 0.f);
                hb[3 * 64 + lane + 32] = fmaxf(p3.y - qhi, 0.f);
                __syncwarp();

                ull a0s0 = 0, a1s0 = 0, c0s0 = 0, c1s0 = 0;
                ull a0s1 = 0, a1s1 = 0, c0s1 = 0, c1s1 = 0;
                ull a0s2 = 0, a1s2 = 0, c0s2 = 0, c1s2 = 0;
                ull a0s3 = 0, a1s3 = 0, c0s3 = 0, c1s3 = 0;
                const double2* h0 = (const double2*)(hb + 0 * 64);
                const double2* h1 = (const double2*)(hb + 1 * 64);
                const double2* h2 = (const double2*)(hb + 2 * 64);
                const double2* h3 = (const double2*)(hb + 3 * 64);
#pragma unroll
                for (int jj = 0; jj < 8; jj++) {
                    double2 dAlo = *(const double2*)&w2b[2 * jj][lane][0];
                    double2 dBlo = *(const double2*)&w2b[2 * jj + 1][lane][0];
                    double2 dAhi = *(const double2*)&w2b[2 * jj][lane + 32][0];
                    double2 dBhi = *(const double2*)&w2b[2 * jj + 1][lane + 32][0];
                    ull wl0 = d2u(dAlo.x), wl1 = d2u(dAlo.y);
                    ull wl2 = d2u(dBlo.x), wl3 = d2u(dBlo.y);
                    ull wh0 = d2u(dAhi.x), wh1 = d2u(dAhi.y);
                    ull wh2 = d2u(dBhi.x), wh3 = d2u(dBhi.y);
                    double2 v0 = h0[2 * jj], v1 = h0[2 * jj + 1];
                    double2 u0 = h1[2 * jj], u1 = h1[2 * jj + 1];
                    double2 x0 = h2[2 * jj], x1 = h2[2 * jj + 1];
                    double2 y0 = h3[2 * jj], y1 = h3[2 * jj + 1];
                    fma2(a0s0, d2u(v0.x), wl0); fma2(a1s0, d2u(v0.y), wl1);
                    fma2(a0s0, d2u(v1.x), wl2); fma2(a1s0, d2u(v1.y), wl3);
                    fma2(c0s0, d2u(v0.x), wh0); fma2(c1s0, d2u(v0.y), wh1);
                    fma2(c0s0, d2u(v1.x), wh2); fma2(c1s0, d2u(v1.y), wh3);
                    fma2(a0s1, d2u(u0.x), wl0); fma2(a1s1, d2u(u0.y), wl1);
                    fma2(a0s1, d2u(u1.x), wl2); fma2(a1s1, d2u(u1.y), wl3);
                    fma2(c0s1, d2u(u0.x), wh0); fma2(c1s1, d2u(u0.y), wh1);
                    fma2(c0s1, d2u(u1.x), wh2); fma2(c1s1, d2u(u1.y), wh3);
                    fma2(a0s2, d2u(x0.x), wl0); fma2(a1s2, d2u(x0.y), wl1);
                    fma2(a0s2, d2u(x1.x), wl2); fma2(a1s2, d2u(x1.y), wl3);
                    fma2(c0s2, d2u(x0.x), wh0); fma2(c1s2, d2u(x0.y), wh1);
                    fma2(c0s2, d2u(x1.x), wh2); fma2(c1s2, d2u(x1.y), wh3);
                    fma2(a0s3, d2u(y0.x), wl0); fma2(a1s3, d2u(y0.y), wl1);
                    fma2(a0s3, d2u(y1.x), wl2); fma2(a1s3, d2u(y1.y), wl3);
                    fma2(c0s3, d2u(y0.x), wh0); fma2(c1s3, d2u(y0.y), wh1);
                    fma2(c0s3, d2u(y1.x), wh2); fma2(c1s3, d2u(y1.y), wh3);
                }
                __syncwarp();

                float2 p, q;
                p = unpack2(a0s0); q = unpack2(a1s0);
                mxA = fmaxf(mxA, fmaf(g2lo, (p.x + p.y) + (q.x + q.y), b2lo));
                p = unpack2(c0s0); q = unpack2(c1s0);
                mxB = fmaxf(mxB, fmaf(g2hi, (p.x + p.y) + (q.x + q.y), b2hi));
                p = unpack2(a0s1); q = unpack2(a1s1);
                mxA = fmaxf(mxA, fmaf(g2lo, (p.x + p.y) + (q.x + q.y), b2lo));
                p = unpack2(c0s1); q = unpack2(c1s1);
                mxB = fmaxf(mxB, fmaf(g2hi, (p.x + p.y) + (q.x + q.y), b2hi));
                p = unpack2(a0s2); q = unpack2(a1s2);
                mxA = fmaxf(mxA, fmaf(g2lo, (p.x + p.y) + (q.x + q.y), b2lo));
                p = unpack2(c0s2); q = unpack2(c1s2);
                mxB = fmaxf(mxB, fmaf(g2hi, (p.x + p.y) + (q.x + q.y), b2hi));
                p = unpack2(a0s3); q = unpack2(a1s3);
                mxA = fmaxf(mxA, fmaf(g2lo, (p.x + p.y) + (q.x + q.y), b2lo));
                p = unpack2(c0s3); q = unpack2(c1s3);
                mxB = fmaxf(mxB, fmaf(g2hi, (p.x + p.y) + (q.x + q.y), b2hi));

                p0 = q0; p1 = q1; p2 = q2v; p3 = q3;
            }
            int ni = g / N_GRIDP, mi = g % N_GRIDP;
            int cpA = b * 64 + lane;
            d_perm[mi * 16384 + cpA * 128 + ni] = fmaxf(mxA, 0.f);
            d_perm[mi * 16384 + (cpA + 32) * 128 + ni] = fmaxf(mxB, 0.f);
        }
    }
}

// ---------------- k5: reduction GEMM layer1, split-K=72, f32x2 ----------------
__global__ void __launch_bounds__(256) k_red1(const float* __restrict__ W)
{
    __shared__ __align__(16) float As[32][132];
    __shared__ __align__(16) float Bs[32][68];
    const int ob = blockIdx.x * 64;
    const int kbase = blockIdx.y * KCHUNK;
    const int tid = threadIdx.x;
    const int tx = tid & 15, ty = tid >> 4;

    ull acc[4][4];
#pragma unroll
    for (int r = 0; r < 4; r++)
#pragma unroll
        for (int c = 0; c < 4; c++) acc[r][c] = 0;

    for (int kc = 0; kc < KCHUNK; kc += 32) {
        int k0 = kbase + kc;
#pragma unroll
        for (int r = 0; r < 16; r++) {
            int e = tid + 256 * r;
            int i = e >> 5, kk = e & 31;
            As[kk][i] = d_perm[i * K_RED + k0 + kk];
        }
#pragma unroll
        for (int r = 0; r < 8; r++) {
            int e = tid + 256 * r;
            int o = e >> 5, kk = e & 31;
            Bs[kk][o] = W[(ob + o) * K_RED + k0 + kk];
        }
        __syncthreads();
#pragma unroll
        for (int kk = 0; kk < 32; kk++) {
            double2 a01 = *(const double2*)&As[kk][ty * 8];
            double2 a23 = *(const double2*)&As[kk][ty * 8 + 4];
            float4 bv = *(const float4*)&Bs[kk][tx * 4];
            ull ap0 = d2u(a01.x), ap1 = d2u(a01.y), ap2 = d2u(a23.x), ap3 = d2u(a23.y);
            ull b0 = splat2(bv.x), b1 = splat2(bv.y), b2 = splat2(bv.z), b3 = splat2(bv.w);
            fma2(acc[0][0], ap0, b0); fma2(acc[0][1], ap0, b1); fma2(acc[0][2], ap0, b2); fma2(acc[0][3], ap0, b3);
            fma2(acc[1][0], ap1, b0); fma2(acc[1][1], ap1, b1); fma2(acc[1][2], ap1, b2); fma2(acc[1][3], ap1, b3);
            fma2(acc[2][0], ap2, b0); fma2(acc[2][1], ap2, b1); fma2(acc[2][2], ap2, b2); fma2(acc[2][3], ap2, b3);
            fma2(acc[3][0], ap3, b0); fma2(acc[3][1], ap3, b1); fma2(acc[3][2], ap3, b2); fma2(acc[3][3], ap3, b3);
        }
        __syncthreads();
    }
    float* outp = d_partial[blockIdx.y];
#pragma unroll
    for (int rp = 0; rp < 4; rp++)
#pragma unroll
        for (int c = 0; c < 4; c++) {
            float2 v = unpack2(acc[rp][c]);
            outp[(ty * 8 + 2 * rp) * 256 + ob + tx * 4 + c] = v.x;
            outp[(ty * 8 + 2 * rp + 1) * 256 + ob + tx * 4 + c] = v.y;
        }
}

// ---------------- k6: partial reduce + bias + relu ----------------
__global__ void k_redfin(const float* __restrict__ b1)
{
    int t = blockIdx.x * 256 + threadIdx.x;
    float s = b1[t & 255];
#pragma unroll
    for (int ks = 0; ks < KSPLIT; ks++) s += d_partial[ks][t];
    d_hbuf[t] = fmaxf(s, 0.f);
}

// ---------------- k6b: transpose W2 ----------------
__global__ void k_w2t(const float* __restrict__ W2)
{
    __shared__ float tbuf[32][33];
    int x = blockIdx.x * 32 + threadIdx.x;
    int y0 = blockIdx.y * 32;
#pragma unroll
    for (int r = threadIdx.y; r < 32; r += 8)
        tbuf[r][threadIdx.x] = W2[(y0 + r) * 256 + x];
    __syncthreads();
    int xo = blockIdx.y * 32 + threadIdx.x;
#pragma unroll
    for (int r = threadIdx.y; r < 32; r += 8)
        d_w2t[(blockIdx.x * 32 + r) * 256 + xo] = tbuf[threadIdx.x][r];
}

// ---------------- k7: layer2 256x256 + relu ----------------
__global__ void __launch_bounds__(256) k_red2(const float* __restrict__ b2, float* __restrict__ out)
{
    __shared__ float hs[256];
    int i = blockIdx.x;
    hs[threadIdx.x] = d_hbuf[i * 256 + threadIdx.x];
    __syncthreads();
    int o = threadIdx.x;
    float s = b2[o];
#pragma unroll 8
    for (int c = 0; c < 256; c++) s = fmaf(hs[c], d_w2t[c * 256 + o], s);
    out[i * 256 + o] = fmaxf(s, 0.f);
}

// ---------------- launch ----------------
extern "C" void kernel_launch(void* const* d_in, const int* in_sizes, int n_in,
                              void* d_out, int out_size)
{
    const float* wlh    = (const float*)d_in[0];
    const float* center = (const float*)d_in[1];
    const float* yaw    = (const float*)d_in[2];
    const float* u      = (const float*)d_in[3];
    const float* kp     = (const float*)d_in[4];
    const float* kf     = (const float*)d_in[5];
    const float* pn0_w1 = (const float*)d_in[6];
    const float* pn0_g1 = (const float*)d_in[7];
    const float* pn0_b1 = (const float*)d_in[8];
    const float* pn0_w2 = (const float*)d_in[9];
    const float* pn0_g2 = (const float*)d_in[10];
    const float* pn0_b2 = (const float*)d_in[11];
    const float* pn1_w1 = (const float*)d_in[12];
    const float* pn1_g1 = (const float*)d_in[13];
    const float* pn1_b1 = (const float*)d_in[14];
    const float* pn1_w2 = (const float*)d_in[15];
    const float* pn1_g2 = (const float*)d_in[16];
    const float* pn1_b2 = (const float*)d_in[17];
    const float* red_w1 = (const float*)d_in[18];
    const float* red_b1 = (const float*)d_in[19];
    const float* red_w2 = (const float*)d_in[20];
    const float* red_b2 = (const float*)d_in[21];
    float* out = (float*)d_out;

    cudaFuncSetAttribute(k_ball, cudaFuncAttributeMaxDynamicSharedMemorySize, 66048);
    cudaFuncSetAttribute(k_A,    cudaFuncAttributeMaxDynamicSharedMemorySize, 32768);

    k_grid<<<(G_TOT + 255) / 256, 256>>>(wlh, center, yaw, u);
    k_ball<<<148, BQ_THREADS, 66048>>>(kp);
    k_A<<<dim3(64, 2), dim3(32, 8), 32768>>>(kp, kf, pn0_w1, pn1_w1,
                                             pn0_g1, pn1_g1, pn0_b1, pn1_b1);
    k_branch<<<296, 256>>>(pn0_w1, pn0_g1, pn0_w2, pn0_g2, pn0_b2,
                           pn1_w1, pn1_g1, pn1_w2, pn1_g2, pn1_b2);
    k_w2t<<<dim3(8, 8), dim3(32, 8)>>>(red_w2);
    k_red1<<<dim3(4, KSPLIT), 256>>>(red_w1);
    k_redfin<<<128, 256>>>(red_b1);
    k_red2<<<128, 256>>>(red_b2, out);
}

// round 16
// speedup vs baseline: 1.1763x; 1.0425x over previous
#include <cuda_runtime.h>
#include <cuda_bf16.h>

#define N_PROP 128
#define N_GRIDP 216
#define G_TOT  27648
#define N_KEY  4096
#define C_FEAT 128
#define NS     16
#define K_RED  27648
#define KSPLIT 72
#define KCHUNK 384
#define NCHUNK 3456              // 2 * 27648 / 16
#define BQ_THREADS 512
#define BQ_CHUNKS 1728

typedef unsigned long long ull;

// ---------------- scratch ----------------
static __device__ float  d_grid[G_TOT * 3];
static __device__ float2 d_A[2][N_KEY * 32];    // A' = g1*A + b1, packed (c, c+32)
static __device__ int    d_idx[2][G_TOT * NS];
static __device__ int    d_cnt[2][G_TOT];
static __device__ float  d_perm[N_PROP * K_RED];
static __device__ float  d_partial[KSPLIT][N_PROP * 256];
static __device__ float  d_hbuf[N_PROP * 256];
static __device__ float  d_w2t[256 * 256];
static __device__ unsigned d_work;

// ---------------- f32x2 helpers ----------------
__device__ __forceinline__ ull splat2(float x) {
    ull r;
    asm("mov.b64 %0, {%1, %1};" : "=l"(r) : "f"(x));
    return r;
}
__device__ __forceinline__ void fma2(ull& acc, ull a, ull b) {
    asm("fma.rn.f32x2 %0, %1, %2, %0;" : "+l"(acc) : "l"(a), "l"(b));
}
__device__ __forceinline__ float2 unpack2(ull v) {
    float lo, hi;
    asm("mov.b64 {%0, %1}, %2;" : "=f"(lo), "=f"(hi) : "l"(v));
    return make_float2(lo, hi);
}
__device__ __forceinline__ ull d2u(double d) { return __double_as_longlong(d); }

// ---------------- k1: grid points (+ work counter reset) ----------------
__global__ void k_grid(const float* __restrict__ wlh, const float* __restrict__ center,
                       const float* __restrict__ yaw, const float* __restrict__ u)
{
    if (blockIdx.x == 0 && threadIdx.x == 0) d_work = 0u;
    int g = blockIdx.x * 256 + threadIdx.x;
    if (g >= G_TOT) return;
    int ni = g / N_GRIDP;
    float gx = u[g * 3 + 0] * wlh[ni * 3 + 0];
    float gy = u[g * 3 + 1] * wlh[ni * 3 + 1];
    float gz = u[g * 3 + 2] * wlh[ni * 3 + 2];
    float yv = yaw[ni];
    float c = cosf(yv), s = sinf(yv);
    float rx = c * gx - s * gy;
    float ry = s * gx + c * gy;
    d_grid[g * 3 + 0] = rx + center[ni * 3 + 0];
    d_grid[g * 3 + 1] = ry + center[ni * 3 + 1];
    d_grid[g * 3 + 2] = gz + center[ni * 3 + 2];
}

// ---------------- k2: per-keypoint A' = g1*(kp.w1[:3] + kf.w1[3:]) + b1 -------
__global__ void __launch_bounds__(256) k_A(const float* __restrict__ kp, const float* __restrict__ kf,
                                           const float* __restrict__ w1_0, const float* __restrict__ w1_1,
                                           const float* __restrict__ g1_0, const float* __restrict__ g1_1,
                                           const float* __restrict__ b1_0, const float* __restrict__ b1_1)
{
    __shared__ float w1s[64 * 131];
    extern __shared__ float kfs[];            // 128 c x 64 k = 32 KB dynamic
    const float* w1 = blockIdx.y ? w1_1 : w1_0;
    const float* g1 = blockIdx.y ? g1_1 : g1_0;
    const float* b1 = blockIdx.y ? b1_1 : b1_0;
    int tid = threadIdx.y * 32 + threadIdx.x;
    for (int i = tid; i < 64 * 131; i += 256) w1s[i] = w1[i];

    int kbase = blockIdx.x * 64;
    for (int e = tid; e < C_FEAT * 64; e += 256) {
        int c = e >> 6, kk = e & 63;
        kfs[c * 64 + kk] = kf[c * N_KEY + kbase + kk];
    }
    __syncthreads();

    int l = threadIdx.x;
    float g1lo = g1[l], g1hi = g1[l + 32];
    float b1lo = b1[l], b1hi = b1[l + 32];
#pragma unroll 1
    for (int t = 0; t < 8; t++) {
        int kk = t * 8 + threadIdx.y;
        int k = kbase + kk;
        float kx = kp[k * 3 + 0], ky = kp[k * 3 + 1], kz = kp[k * 3 + 2];
        float a0 = w1s[l * 131 + 0] * kx + w1s[l * 131 + 1] * ky + w1s[l * 131 + 2] * kz;
        float a1 = w1s[(l + 32) * 131 + 0] * kx + w1s[(l + 32) * 131 + 1] * ky + w1s[(l + 32) * 131 + 2] * kz;
#pragma unroll 4
        for (int c = 0; c < C_FEAT; c++) {
            float f = kfs[c * 64 + kk];
            a0 = fmaf(f, w1s[l * 131 + 3 + c], a0);
            a1 = fmaf(f, w1s[(l + 32) * 131 + 3 + c], a1);
        }
        d_A[blockIdx.y][k * 32 + l] = make_float2(fmaf(g1lo, a0, b1lo), fmaf(g1hi, a1, b1hi));
    }
}

// ---------------- k3: warp-cooperative ball query, PERSISTENT ----------------
__device__ __forceinline__ void bq_merge(int* __restrict__ out, int* __restrict__ cntout,
                                         int c, const int* h, int lane)
{
    const unsigned full = 0xffffffffu;
    int pre = c;
#pragma unroll
    for (int off = 1; off < 32; off <<= 1) {
        int t = __shfl_up_sync(full, pre, off);
        if (lane >= off) pre += t;
    }
    int excl = pre - c;
    int total = __shfl_sync(full, pre, 31);
    unsigned ball = __ballot_sync(full, c > 0);
    int myfirst = lane * 128 + h[0];
    int fl = (ball != 0u) ? (__ffs(ball) - 1) : 0;
    int f = __shfl_sync(full, myfirst, fl);
    if (ball == 0u) f = 0;
#pragma unroll 1
    for (int t = 0; t < c; t++) {
        int pos = excl + t;
        if (pos < NS) out[pos] = lane * 128 + h[t];
    }
    int tot16 = (total < NS) ? total : NS;
    for (int p = tot16 + lane; p < NS; p += 32) out[p] = f;
    if (lane == 0) *cntout = (tot16 > 0) ? tot16 : 1;
}

__global__ void __launch_bounds__(BQ_THREADS) k_ball(const float* __restrict__ kp)
{
    extern __shared__ float4 kpt[];   // [lane*129 + i], 4128 float4 = 66048 B
    int tid = threadIdx.x;
    for (int k = tid; k < N_KEY; k += BQ_THREADS) {
        int l = k >> 7, i = k & 127;
        float kx = kp[k * 3 + 0], ky = kp[k * 3 + 1], kz = kp[k * 3 + 2];
        kpt[l * 129 + i] = make_float4(kx, ky, kz, kx * kx + ky * ky + kz * kz);
    }
    __syncthreads();

    int lane = tid & 31, warp = tid >> 5;
    const float4* my = kpt + lane * 129;

#pragma unroll 1
    for (int t = blockIdx.x; t < BQ_CHUNKS; t += 148) {
        int g = t * (BQ_THREADS / 32) + warp;

        float gx = d_grid[g * 3 + 0], gy = d_grid[g * 3 + 1], gz = d_grid[g * 3 + 2];
        float gs = gx * gx + gy * gy + gz * gz;
        float m2x = -2.f * gx, m2y = -2.f * gy, m2z = -2.f * gz;

        int h0[NS], h1[NS];
        h0[0] = 0; h1[0] = 0;
        int c0 = 0, c1 = 0;

#pragma unroll 1
        for (int i = 0; i < 128; i += 4) {
            float4 v0 = my[i + 0];
            float4 v1 = my[i + 1];
            float4 v2 = my[i + 2];
            float4 v3 = my[i + 3];
            float d20 = fmaf(m2x, v0.x, fmaf(m2y, v0.y, fmaf(m2z, v0.z, gs + v0.w)));
            float d21 = fmaf(m2x, v1.x, fmaf(m2y, v1.y, fmaf(m2z, v1.z, gs + v1.w)));
            float d22 = fmaf(m2x, v2.x, fmaf(m2y, v2.y, fmaf(m2z, v2.z, gs + v2.w)));
            float d23 = fmaf(m2x, v3.x, fmaf(m2y, v3.y, fmaf(m2z, v3.z, gs + v3.w)));
            if (fminf(fminf(d20, d21), fminf(d22, d23)) < 2.56f) {   // rare
                if (d20 < 2.56f) { if (c1 < NS) h1[c1++] = i + 0; if (d20 < 0.64f && c0 < NS) h0[c0++] = i + 0; }
                if (d21 < 2.56f) { if (c1 < NS) h1[c1++] = i + 1; if (d21 < 0.64f && c0 < NS) h0[c0++] = i + 1; }
                if (d22 < 2.56f) { if (c1 < NS) h1[c1++] = i + 2; if (d22 < 0.64f && c0 < NS) h0[c0++] = i + 2; }
                if (d23 < 2.56f) { if (c1 < NS) h1[c1++] = i + 3; if (d23 < 0.64f && c0 < NS) h0[c0++] = i + 3; }
            }
        }
        bq_merge(&d_idx[0][g * NS], &d_cnt[0][g], c0, h0, lane);
        bq_merge(&d_idx[1][g * NS], &d_cnt[1][g], c1, h1, lane);
    }
}

// ---------------- k4: branch MLP + maxpool, adaptive 4/8-sample groups -------
// warp per gridpoint, lane owns channels (lane, lane+32).
// w2 in smem [b][c/4][o][4]; group-size 8 when cnt>4 halves w2 crossbar traffic.
// acc per sample merged to 2 chains (accLo, accHi) to stay <=128 regs @ 2 CTA/SM.
__device__ __forceinline__ void kb_group(
    const float2* p, int nsmp, float* hb,
    const float (*w2b)[64][4], int lane,
    float qlo, float qhi, float g2lo, float g2hi, float b2lo, float b2hi,
    float& mxA, float& mxB)
{
#pragma unroll
    for (int s = 0; s < 8; s++) {
        if (s < nsmp) {
            hb[s * 64 + lane]      = fmaxf(p[s].x - qlo, 0.f);
            hb[s * 64 + lane + 32] = fmaxf(p[s].y - qhi, 0.f);
        }
    }
    __syncwarp();

    ull accLo[8], accHi[8];
#pragma unroll
    for (int s = 0; s < 8; s++) { accLo[s] = 0; accHi[s] = 0; }

#pragma unroll
    for (int jj = 0; jj < 8; jj++) {
        double2 dAlo = *(const double2*)&w2b[2 * jj][lane][0];
        double2 dBlo = *(const double2*)&w2b[2 * jj + 1][lane][0];
        double2 dAhi = *(const double2*)&w2b[2 * jj][lane + 32][0];
        double2 dBhi = *(const double2*)&w2b[2 * jj + 1][lane + 32][0];
        ull wl0 = d2u(dAlo.x), wl1 = d2u(dAlo.y);
        ull wl2 = d2u(dBlo.x), wl3 = d2u(dBlo.y);
        ull wh0 = d2u(dAhi.x), wh1 = d2u(dAhi.y);
        ull wh2 = d2u(dBhi.x), wh3 = d2u(dBhi.y);
#pragma unroll
        for (int s = 0; s < 8; s++) {
            if (s < nsmp) {
                const double2* hs = (const double2*)(hb + s * 64);
                double2 v0 = hs[2 * jj], v1 = hs[2 * jj + 1];
                fma2(accLo[s], d2u(v0.x), wl0); fma2(accLo[s], d2u(v0.y), wl1);
                fma2(accLo[s], d2u(v1.x), wl2); fma2(accLo[s], d2u(v1.y), wl3);
                fma2(accHi[s], d2u(v0.x), wh0); fma2(accHi[s], d2u(v0.y), wh1);
                fma2(accHi[s], d2u(v1.x), wh2); fma2(accHi[s], d2u(v1.y), wh3);
            }
        }
    }
    __syncwarp();

#pragma unroll
    for (int s = 0; s < 8; s++) {
        if (s < nsmp) {
            float2 pl = unpack2(accLo[s]);
            float2 ph = unpack2(accHi[s]);
            mxA = fmaxf(mxA, fmaf(g2lo, pl.x + pl.y, b2lo));
            mxB = fmaxf(mxB, fmaf(g2hi, ph.x + ph.y, b2hi));
        }
    }
}

__global__ void __launch_bounds__(256, 2) k_branch(
    const float* __restrict__ w1_0, const float* __restrict__ g1_0,
    const float* __restrict__ w2_0, const float* __restrict__ g2_0, const float* __restrict__ b2_0,
    const float* __restrict__ w1_1, const float* __restrict__ g1_1,
    const float* __restrict__ w2_1, const float* __restrict__ g2_1, const float* __restrict__ b2_1)
{
    const int lane = threadIdx.x & 31;
    const int warp = threadIdx.x >> 5;
    const int tid  = threadIdx.x;

    __shared__ __align__(16) float w2s[2][16][64][4];   // 32 KB static
    extern __shared__ __align__(16) float dynbuf[];     // 8 warps x 8 smp x 64 = 16 KB
    __shared__ int s_chunk;
    float* hb = dynbuf + warp * 8 * 64;

    for (int e = tid; e < 2 * 64 * 64; e += 256) {
        int b = e >> 12, r = e & 4095, o = r >> 6, c = r & 63;
        const float* w2 = b ? w2_1 : w2_0;
        w2s[b][c >> 2][o][c & 3] = w2[o * 64 + c];
    }

    int cur_b = -1;
    float g2lo = 0, g2hi = 0, b2lo = 0, b2hi = 0;
    float g1lo = 0, g1hi = 0;
    float w1x0 = 0, w1y0 = 0, w1z0 = 0, w1x1 = 0, w1y1 = 0, w1z1 = 0;
    const float2* A2 = d_A[0];
    const int*    idxp = d_idx[0];
    const int*    cntp = d_cnt[0];

    for (;;) {
        __syncthreads();
        if (tid == 0) s_chunk = (int)atomicAdd(&d_work, 1u);
        __syncthreads();
        int chunk = s_chunk;
        if (chunk >= NCHUNK) break;

        int b = (chunk >= NCHUNK / 2);
        int gbase = (chunk - b * (NCHUNK / 2)) * 16;

        if (b != cur_b) {
            cur_b = b;
            const float* w1 = b ? w1_1 : w1_0;
            const float* g1 = b ? g1_1 : g1_0;
            const float* g2 = b ? g2_1 : g2_0;
            const float* b2 = b ? b2_1 : b2_0;
            g2lo = g2[lane]; g2hi = g2[lane + 32];
            b2lo = b2[lane]; b2hi = b2[lane + 32];
            g1lo = g1[lane]; g1hi = g1[lane + 32];
            w1x0 = w1[lane * 131 + 0]; w1y0 = w1[lane * 131 + 1]; w1z0 = w1[lane * 131 + 2];
            w1x1 = w1[(lane + 32) * 131 + 0]; w1y1 = w1[(lane + 32) * 131 + 1]; w1z1 = w1[(lane + 32) * 131 + 2];
            A2 = d_A[b];
            idxp = d_idx[b];
            cntp = d_cnt[b];
        }

        const float (*w2b)[64][4] = w2s[b];

#pragma unroll 1
        for (int gi = 0; gi < 2; gi++) {
            int g = gbase + warp * 2 + gi;
            float gx = d_grid[g * 3 + 0], gy = d_grid[g * 3 + 1], gz = d_grid[g * 3 + 2];
            float qlo = g1lo * (w1x0 * gx + w1y0 * gy + w1z0 * gz);
            float qhi = g1hi * (w1x1 * gx + w1y1 * gy + w1z1 * gz);
            int cnt = cntp[g];
            int cm1 = cnt - 1;
            int kreg = idxp[g * NS + (lane & 15)];
            float mxA = -1e30f, mxB = -1e30f;

            float2 p[8];
            if (cnt <= 4) {
#pragma unroll
                for (int s = 0; s < 4; s++) {
                    int idx = (s < cm1) ? s : cm1;
                    p[s] = A2[__shfl_sync(0xffffffffu, kreg, idx) * 32 + lane];
                }
                kb_group(p, 4, hb, w2b, lane, qlo, qhi, g2lo, g2hi, b2lo, b2hi, mxA, mxB);
            } else {
#pragma unroll
                for (int s = 0; s < 8; s++) {
                    int idx = (s < cm1) ? s : cm1;
                    p[s] = A2[__shfl_sync(0xffffffffu, kreg, idx) * 32 + lane];
                }
                kb_group(p, 8, hb, w2b, lane, qlo, qhi, g2lo, g2hi, b2lo, b2hi, mxA, mxB);
                if (cnt > 8) {
#pragma unroll
                    for (int s = 0; s < 8; s++) {
                        int idx = (8 + s < cm1) ? 8 + s : cm1;
                        p[s] = A2[__shfl_sync(0xffffffffu, kreg, idx) * 32 + lane];
                    }
                    kb_group(p, 8, hb, w2b, lane, qlo, qhi, g2lo, g2hi, b2lo, b2hi, mxA, mxB);
                }
            }

            int ni = g / N_GRIDP, mi = g % N_GRIDP;
            int cpA = b * 64 + lane;
            d_perm[mi * 16384 + cpA * 128 + ni] = fmaxf(mxA, 0.f);
            d_perm[mi * 16384 + (cpA + 32) * 128 + ni] = fmaxf(mxB, 0.f);
        }
    }
}

// ---------------- k5: reduction GEMM layer1, split-K=72, f32x2 ----------------
__global__ void __launch_bounds__(256) k_red1(const float* __restrict__ W)
{
    __shared__ __align__(16) float As[32][132];
    __shared__ __align__(16) float Bs[32][68];
    const int ob = blockIdx.x * 64;
    const int kbase = blockIdx.y * KCHUNK;
    const int tid = threadIdx.x;
    const int tx = tid & 15, ty = tid >> 4;

    ull acc[4][4];
#pragma unroll
    for (int r = 0; r < 4; r++)
#pragma unroll
        for (int c = 0; c < 4; c++) acc[r][c] = 0;

    for (int kc = 0; kc < KCHUNK; kc += 32) {
        int k0 = kbase + kc;
#pragma unroll
        for (int r = 0; r < 16; r++) {
            int e = tid + 256 * r;
            int i = e >> 5, kk = e & 31;
            As[kk][i] = d_perm[i * K_RED + k0 + kk];
        }
#pragma unroll
        for (int r = 0; r < 8; r++) {
            int e = tid + 256 * r;
            int o = e >> 5, kk = e & 31;
            Bs[kk][o] = W[(ob + o) * K_RED + k0 + kk];
        }
        __syncthreads();
#pragma unroll
        for (int kk = 0; kk < 32; kk++) {
            double2 a01 = *(const double2*)&As[kk][ty * 8];
            double2 a23 = *(const double2*)&As[kk][ty * 8 + 4];
            float4 bv = *(const float4*)&Bs[kk][tx * 4];
            ull ap0 = d2u(a01.x), ap1 = d2u(a01.y), ap2 = d2u(a23.x), ap3 = d2u(a23.y);
            ull b0 = splat2(bv.x), b1 = splat2(bv.y), b2 = splat2(bv.z), b3 = splat2(bv.w);
            fma2(acc[0][0], ap0, b0); fma2(acc[0][1], ap0, b1); fma2(acc[0][2], ap0, b2); fma2(acc[0][3], ap0, b3);
            fma2(acc[1][0], ap1, b0); fma2(acc[1][1], ap1, b1); fma2(acc[1][2], ap1, b2); fma2(acc[1][3], ap1, b3);
            fma2(acc[2][0], ap2, b0); fma2(acc[2][1], ap2, b1); fma2(acc[2][2], ap2, b2); fma2(acc[2][3], ap2, b3);
            fma2(acc[3][0], ap3, b0); fma2(acc[3][1], ap3, b1); fma2(acc[3][2], ap3, b2); fma2(acc[3][3], ap3, b3);
        }
        __syncthreads();
    }
    float* outp = d_partial[blockIdx.y];
#pragma unroll
    for (int rp = 0; rp < 4; rp++)
#pragma unroll
        for (int c = 0; c < 4; c++) {
            float2 v = unpack2(acc[rp][c]);
            outp[(ty * 8 + 2 * rp) * 256 + ob + tx * 4 + c] = v.x;
            outp[(ty * 8 + 2 * rp + 1) * 256 + ob + tx * 4 + c] = v.y;
        }
}

// ---------------- k6: partial reduce + bias + relu ----------------
__global__ void k_redfin(const float* __restrict__ b1)
{
    int t = blockIdx.x * 256 + threadIdx.x;
    float s = b1[t & 255];
#pragma unroll
    for (int ks = 0; ks < KSPLIT; ks++) s += d_partial[ks][t];
    d_hbuf[t] = fmaxf(s, 0.f);
}

// ---------------- k6b: transpose W2 ----------------
__global__ void k_w2t(const float* __restrict__ W2)
{
    __shared__ float tbuf[32][33];
    int x = blockIdx.x * 32 + threadIdx.x;
    int y0 = blockIdx.y * 32;
#pragma unroll
    for (int r = threadIdx.y; r < 32; r += 8)
        tbuf[r][threadIdx.x] = W2[(y0 + r) * 256 + x];
    __syncthreads();
    int xo = blockIdx.y * 32 + threadIdx.x;
#pragma unroll
    for (int r = threadIdx.y; r < 32; r += 8)
        d_w2t[(blockIdx.x * 32 + r) * 256 + xo] = tbuf[threadIdx.x][r];
}

// ---------------- k7: layer2 256x256 + relu ----------------
__global__ void __launch_bounds__(256) k_red2(const float* __restrict__ b2, float* __restrict__ out)
{
    __shared__ float hs[256];
    int i = blockIdx.x;
    hs[threadIdx.x] = d_hbuf[i * 256 + threadIdx.x];
    __syncthreads();
    int o = threadIdx.x;
    float s = b2[o];
#pragma unroll 8
    for (int c = 0; c < 256; c++) s = fmaf(hs[c], d_w2t[c * 256 + o], s);
    out[i * 256 + o] = fmaxf(s, 0.f);
}

// ---------------- launch ----------------
extern "C" void kernel_launch(void* const* d_in, const int* in_sizes, int n_in,
                              void* d_out, int out_size)
{
    const float* wlh    = (const float*)d_in[0];
    const float* center = (const float*)d_in[1];
    const float* yaw    = (const float*)d_in[2];
    const float* u      = (const float*)d_in[3];
    const float* kp     = (const float*)d_in[4];
    const float* kf     = (const float*)d_in[5];
    const float* pn0_w1 = (const float*)d_in[6];
    const float* pn0_g1 = (const float*)d_in[7];
    const float* pn0_b1 = (const float*)d_in[8];
    const float* pn0_w2 = (const float*)d_in[9];
    const float* pn0_g2 = (const float*)d_in[10];
    const float* pn0_b2 = (const float*)d_in[11];
    const float* pn1_w1 = (const float*)d_in[12];
    const float* pn1_g1 = (const float*)d_in[13];
    const float* pn1_b1 = (const float*)d_in[14];
    const float* pn1_w2 = (const float*)d_in[15];
    const float* pn1_g2 = (const float*)d_in[16];
    const float* pn1_b2 = (const float*)d_in[17];
    const float* red_w1 = (const float*)d_in[18];
    const float* red_b1 = (const float*)d_in[19];
    const float* red_w2 = (const float*)d_in[20];
    const float* red_b2 = (const float*)d_in[21];
    float* out = (float*)d_out;

    cudaFuncSetAttribute(k_ball, cudaFuncAttributeMaxDynamicSharedMemorySize, 66048);
    cudaFuncSetAttribute(k_A,    cudaFuncAttributeMaxDynamicSharedMemorySize, 32768);
    cudaFuncSetAttribute(k_branch, cudaFuncAttributeMaxDynamicSharedMemorySize, 16384);

    k_grid<<<(G_TOT + 255) / 256, 256>>>(wlh, center, yaw, u);
    k_ball<<<148, BQ_THREADS, 66048>>>(kp);
    k_A<<<dim3(64, 2), dim3(32, 8), 32768>>>(kp, kf, pn0_w1, pn1_w1,
                                             pn0_g1, pn1_g1, pn0_b1, pn1_b1);
    k_branch<<<296, 256, 16384>>>(pn0_w1, pn0_g1, pn0_w2, pn0_g2, pn0_b2,
                                  pn1_w1, pn1_g1, pn1_w2, pn1_g2, pn1_b2);
    k_w2t<<<dim3(8, 8), dim3(32, 8)>>>(red_w2);
    k_red1<<<dim3(4, KSPLIT), 256>>>(red_w1);
    k_redfin<<<128, 256>>>(red_b1);
    k_red2<<<128, 256>>>(red_b2, out);
}